// round 3
// baseline (speedup 1.0000x reference)
#include <cuda_runtime.h>
#include <cstdint>

// Problem constants (fixed by the dataset; scratch sized to max)
#define MAXN 50000
#define D 64

// Scratch (device globals: no allocation allowed). float4 type => 16B aligned.
__device__ float4 g_agg4[MAXN * (D / 4)];
__device__ float  g_deg[MAXN];

// ---------------------------------------------------------------------------
// Kernel 1: zero the scratch buffers (float4 stores for agg)
// ---------------------------------------------------------------------------
__global__ void zero_kernel(int n_nodes) {
    int i = blockIdx.x * blockDim.x + threadIdx.x;
    int n4 = n_nodes * (D / 4);
    if (i < n4) {
        g_agg4[i] = make_float4(0.f, 0.f, 0.f, 0.f);
    }
    if (i < n_nodes) {
        g_deg[i] = 0.f;
    }
}

// ---------------------------------------------------------------------------
// Kernel 2: edge scatter. 16 lanes per edge, each lane handles one float4
// of x[col] and does a vectorized reduction into agg[row]. Lane 0 bumps deg.
// edge_index arrives as int32 (harness converts int64 -> int32).
// ---------------------------------------------------------------------------
__global__ void scatter_kernel(const float* __restrict__ x,
                               const int* __restrict__ ei,
                               int E, int N) {
    int gid = blockIdx.x * blockDim.x + threadIdx.x;
    int edge = gid >> 4;
    int lane = gid & 15;
    if (edge >= E) return;

    // clamp defensively: no-op for valid data, turns dtype bugs into rel_err
    int r = min(max(ei[edge], 0), N - 1);        // destination (row)
    int c = min(max(ei[E + edge], 0), N - 1);    // source (col)

    const float4 v = __ldg(reinterpret_cast<const float4*>(x + (size_t)c * D) + lane);
    float4* dst = g_agg4 + (size_t)r * (D / 4) + lane;
    asm volatile("red.global.add.v4.f32 [%0], {%1, %2, %3, %4};"
                 :: "l"(dst), "f"(v.x), "f"(v.y), "f"(v.z), "f"(v.w)
                 : "memory");
    if (lane == 0) {
        atomicAdd(g_deg + r, 1.0f);
    }
}

// ---------------------------------------------------------------------------
// Kernel 3: fused dual GEMM + bias + degree normalization.
//   out[n][o] = sum_k x[n][k]*Ws[o][k] + (sum_k agg[n][k]*Wn[o][k]) / max(deg[n],1)
//              + bs[o] + bn[o]
// Block = 256 threads handles a 64-node x 64-out tile. Weights transposed in
// shared ([k][o], pad 68 so float4 rows stay 16B-aligned), x/agg tile
// transposed the same way. Each thread computes a 4x4 register tile.
// ---------------------------------------------------------------------------
#define TP 68  // padded row length (floats); 68*4 = 272 bytes, multiple of 16

__global__ __launch_bounds__(256) void sage_gemm_kernel(
    const float* __restrict__ x,
    const float* __restrict__ Ws, const float* __restrict__ bs,
    const float* __restrict__ Wn, const float* __restrict__ bn,
    float* __restrict__ out, int N)
{
    extern __shared__ float sh[];
    float* Wts  = sh;                 // [64][TP]
    float* Wtn  = sh + 64 * TP;       // [64][TP]
    float* xt   = sh + 2 * 64 * TP;   // [64][TP]  (reused: x tile, then agg tile)
    float* bias = sh + 3 * 64 * TP;   // [64]

    const int tid = threadIdx.x;
    const float* agg = reinterpret_cast<const float*>(g_agg4);

    // Load weights transposed into shared (once per block)
    for (int i = tid; i < 64 * 64; i += 256) {
        int o = i >> 6, k = i & 63;
        Wts[k * TP + o] = Ws[i];
        Wtn[k * TP + o] = Wn[i];
    }
    if (tid < 64) bias[tid] = bs[tid] + bn[tid];

    const int to = tid & 15;   // output group: outs 4*to .. 4*to+3
    const int tn = tid >> 4;   // node group:   nodes 4*tn .. 4*tn+3
    const int nTiles = (N + 63) >> 6;

    for (int tile = blockIdx.x; tile < nTiles; tile += gridDim.x) {
        const int node0 = tile << 6;

        __syncthreads();  // weights ready / previous xt consumers done
        // Load x tile transposed: xt[k][n] = x[node0+n][k]
        for (int i = tid; i < 64 * 64; i += 256) {
            int n = i >> 6, k = i & 63;
            int node = node0 + n;
            xt[k * TP + n] = (node < N) ? x[(size_t)node * D + k] : 0.f;
        }
        __syncthreads();

        float acc[4][4];
        #pragma unroll
        for (int i = 0; i < 4; i++)
            #pragma unroll
            for (int j = 0; j < 4; j++) acc[i][j] = 0.f;

        #pragma unroll
        for (int k = 0; k < 64; k++) {
            float4 a = *reinterpret_cast<const float4*>(&xt[k * TP + 4 * tn]);
            float4 w = *reinterpret_cast<const float4*>(&Wts[k * TP + 4 * to]);
            float av[4] = {a.x, a.y, a.z, a.w};
            float wv[4] = {w.x, w.y, w.z, w.w};
            #pragma unroll
            for (int i = 0; i < 4; i++)
                #pragma unroll
                for (int j = 0; j < 4; j++) acc[i][j] += av[i] * wv[j];
        }

        __syncthreads();
        // Reuse xt for the agg tile
        for (int i = tid; i < 64 * 64; i += 256) {
            int n = i >> 6, k = i & 63;
            int node = node0 + n;
            xt[k * TP + n] = (node < N) ? agg[(size_t)node * D + k] : 0.f;
        }
        __syncthreads();

        float accn[4][4];
        #pragma unroll
        for (int i = 0; i < 4; i++)
            #pragma unroll
            for (int j = 0; j < 4; j++) accn[i][j] = 0.f;

        #pragma unroll
        for (int k = 0; k < 64; k++) {
            float4 a = *reinterpret_cast<const float4*>(&xt[k * TP + 4 * tn]);
            float4 w = *reinterpret_cast<const float4*>(&Wtn[k * TP + 4 * to]);
            float av[4] = {a.x, a.y, a.z, a.w};
            float wv[4] = {w.x, w.y, w.z, w.w};
            #pragma unroll
            for (int i = 0; i < 4; i++)
                #pragma unroll
                for (int j = 0; j < 4; j++) accn[i][j] += av[i] * wv[j];
        }

        // Finalize: bias + degree normalization, coalesced float4 stores
        float bj[4];
        #pragma unroll
        for (int j = 0; j < 4; j++) bj[j] = bias[4 * to + j];

        #pragma unroll
        for (int i = 0; i < 4; i++) {
            int node = node0 + 4 * tn + i;
            if (node < N) {
                float inv = 1.0f / fmaxf(g_deg[node], 1.0f);
                float4 r;
                r.x = acc[i][0] + accn[i][0] * inv + bj[0];
                r.y = acc[i][1] + accn[i][1] * inv + bj[1];
                r.z = acc[i][2] + accn[i][2] * inv + bj[2];
                r.w = acc[i][3] + accn[i][3] * inv + bj[3];
                *reinterpret_cast<float4*>(&out[(size_t)node * D + 4 * to]) = r;
            }
        }
    }
}

// ---------------------------------------------------------------------------
// Launch
// ---------------------------------------------------------------------------
extern "C" void kernel_launch(void* const* d_in, const int* in_sizes, int n_in,
                              void* d_out, int out_size) {
    const float* x  = (const float*)d_in[0];
    const int*   ei = (const int*)d_in[1];     // int64 in reference -> int32 on device
    const float* Ws = (const float*)d_in[2];
    const float* bs = (const float*)d_in[3];
    const float* Wn = (const float*)d_in[4];
    const float* bn = (const float*)d_in[5];
    float*       out = (float*)d_out;

    const int N = in_sizes[0] / D;
    const int E = in_sizes[1] / 2;

    // 1) zero scratch
    {
        int threads = N * (D / 4);  // covers agg (float4) and deg (< threads)
        zero_kernel<<<(threads + 255) / 256, 256>>>(N);
    }
    // 2) edge scatter (16 lanes per edge)
    {
        long long total = (long long)E * 16;
        int blocks = (int)((total + 255) / 256);
        scatter_kernel<<<blocks, 256>>>(x, ei, E, N);
    }
    // 3) fused GEMM epilogue
    {
        const int smem = (3 * 64 * TP + 64) * (int)sizeof(float);  // 52480 B
        cudaFuncSetAttribute(sage_gemm_kernel,
                             cudaFuncAttributeMaxDynamicSharedMemorySize, smem);
        int blocks = (N + 63) / 64;
        sage_gemm_kernel<<<blocks, 256, smem>>>(x, Ws, bs, Wn, bn, out, N);
    }
}